// round 11
// baseline (speedup 1.0000x reference)
#include <cuda_runtime.h>

// G2InvariantAttention — GB300 sm_103a — Round 11: work-stealing persistent
// partial.
//   * 2048 items (bh, ks, qblock) handed out by a global atomic counter to
//     exactly 592 resident CTAs (148 SMs x occ 4) -> the 46%-empty last wave
//     (~15% of partial time) collapses to a <=1-item tail.
//   * loop body / regs / smem = R3 verbatim (best measured).
//   * g_work counter reset by the combine kernel (stream-ordered after the
//     partial) -> deterministic across graph replays; capture executes
//     nothing, so state stays consistent.
//   * combine = R10 version (TPB=64, 7.5us, resets g_work).
// Exact math: oct_cross(k,k)=0, v==k, scale folded into q, no max-subtraction
// (logits bounded), linear partial combination via REDG into 2MB acc.

#define N_TOK   2048
#define N_HEAD  16
#define N_BATCH 2
#define DMODEL  128
#define TPB     256
#define CTPB    64
#define KSPLIT  8
#define KCHUNK  (N_TOK / KSPLIT)      // 256 keys per slice
#define NPAIR   (KCHUNK / 2)          // 128 key pairs
#define NITEMS  (N_BATCH * N_HEAD * KSPLIT * (N_TOK / TPB))   // 2048
#define NWORKER 592                   // 148 SMs x occ 4

typedef unsigned long long u64;

// Per-query accumulator: [B*H*N][8 floats] = 2 MB. Zero at load; combine
// re-zeros after reading. Work counter reset by combine each replay.
__device__ float    g_acc[(size_t)N_BATCH * N_HEAD * N_TOK * 8];
__device__ unsigned g_work;

__device__ __forceinline__ u64 f2pack(float lo, float hi) {
    u64 r; asm("mov.b64 %0,{%1,%2};" : "=l"(r) : "f"(lo), "f"(hi)); return r;
}
__device__ __forceinline__ void f2unpack(u64 v, float& lo, float& hi) {
    asm("mov.b64 {%0,%1},%2;" : "=f"(lo), "=f"(hi) : "l"(v));
}
__device__ __forceinline__ u64 f2fma(u64 a, u64 b, u64 c) {
    u64 d; asm("fma.rn.f32x2 %0,%1,%2,%3;" : "=l"(d) : "l"(a), "l"(b), "l"(c)); return d;
}
__device__ __forceinline__ u64 f2mul(u64 a, u64 b) {
    u64 d; asm("mul.rn.f32x2 %0,%1,%2;" : "=l"(d) : "l"(a), "l"(b)); return d;
}
__device__ __forceinline__ u64 f2add(u64 a, u64 b) {
    u64 d; asm("add.rn.f32x2 %0,%1,%2;" : "=l"(d) : "l"(a), "l"(b)); return d;
}
__device__ __forceinline__ float fast_ex2(float x) {
    float r; asm("ex2.approx.f32 %0,%1;" : "=f"(r) : "f"(x)); return r;
}

// ---------------- Kernel 1: persistent work-stealing partial ----------------
__global__ void __launch_bounds__(TPB, 4) g2_attn_partial(
    const float* __restrict__ o, const float* __restrict__ mix)
{
    __shared__ float sP[NPAIR * 16];   // 8 KB, pair-major K slice
    __shared__ unsigned s_item;

    const int tid = threadIdx.x;

    unsigned sbase;
    asm("{ .reg .u64 t; cvta.to.shared.u64 t, %1; cvt.u32.u64 %0, t; }"
        : "=r"(sbase) : "l"(sP));

    for (;;) {
        if (tid == 0) s_item = atomicAdd(&g_work, 1u);
        __syncthreads();                 // publish s_item; fence prior smem reads
        const unsigned item = s_item;
        if (item >= NITEMS) break;

        // Decode: [bh(5)][ks(3)][qb(3)] — consecutive items share (bh,ks).
        const int bh = item >> 6;
        const int ks = (item >> 3) & (KSPLIT - 1);
        const int qb = item & 7;
        const int h  = bh & (N_HEAD - 1);
        const int b  = bh >> 4;
        const float* obase = o + ((size_t)b * N_TOK) * DMODEL + h * 8;

        // Load this item's 256-key slice into pair layout.
        {
            int j  = tid;
            int jg = ks * KCHUNK + j;
            float4 v0 = *(const float4*)(obase + (size_t)jg * DMODEL);
            float4 v1 = *(const float4*)(obase + (size_t)jg * DMODEL + 4);
            float* dst = sP + (j >> 1) * 16 + (j & 1);
            dst[0]  = v0.y;  dst[2]  = v0.z;  dst[4]  = v0.w;  dst[6]  = v1.x;
            dst[8]  = v1.y;  dst[10] = v1.z;  dst[12] = v1.w;  dst[14] = 0.0f;
        }
        __syncthreads();

        const int n = qb * TPB + tid;

        float m0 = mix[2 * h], m1 = mix[2 * h + 1];
        float wk = 1.0f / (1.0f + __expf(m1 - m0));
        const float coef = wk * 1.4426950408889634f * 0.3779644730092272f;

        float4 q0 = *(const float4*)(obase + (size_t)n * DMODEL);
        float4 q1 = *(const float4*)(obase + (size_t)n * DMODEL + 4);
        u64 qd0 = f2pack(q0.y * coef, q0.y * coef);
        u64 qd1 = f2pack(q0.z * coef, q0.z * coef);
        u64 qd2 = f2pack(q0.w * coef, q0.w * coef);
        u64 qd3 = f2pack(q1.x * coef, q1.x * coef);
        u64 qd4 = f2pack(q1.y * coef, q1.y * coef);
        u64 qd5 = f2pack(q1.z * coef, q1.z * coef);
        u64 qd6 = f2pack(q1.w * coef, q1.w * coef);

        u64 a0 = 0ULL, a1 = 0ULL, a2 = 0ULL, a3 = 0ULL,
            a4 = 0ULL, a5 = 0ULL, a6 = 0ULL, l2 = 0ULL;

        unsigned addr = sbase;
        #pragma unroll 2
        for (int p = 0; p < NPAIR; p++, addr += 64) {
            u64 P0, P1, P2, P3, P4, P5, P6, P7;
            asm("ld.shared.v2.b64 {%0,%1},[%2];" : "=l"(P0), "=l"(P1) : "r"(addr));
            asm("ld.shared.v2.b64 {%0,%1},[%2];" : "=l"(P2), "=l"(P3) : "r"(addr + 16));
            asm("ld.shared.v2.b64 {%0,%1},[%2];" : "=l"(P4), "=l"(P5) : "r"(addr + 32));
            asm("ld.shared.v2.b64 {%0,%1},[%2];" : "=l"(P6), "=l"(P7) : "r"(addr + 48));
            (void)P7;
            u64 s = f2mul(qd0, P0);
            s = f2fma(qd1, P1, s);
            s = f2fma(qd2, P2, s);
            s = f2fma(qd3, P3, s);
            s = f2fma(qd4, P4, s);
            s = f2fma(qd5, P5, s);
            s = f2fma(qd6, P6, s);
            float sa, sb; f2unpack(s, sa, sb);
            float ea = fast_ex2(sa);
            float eb = fast_ex2(sb);
            u64 e2 = f2pack(ea, eb);
            a0 = f2fma(P0, e2, a0);
            a1 = f2fma(P1, e2, a1);
            a2 = f2fma(P2, e2, a2);
            a3 = f2fma(P3, e2, a3);
            a4 = f2fma(P4, e2, a4);
            a5 = f2fma(P5, e2, a5);
            a6 = f2fma(P6, e2, a6);
            l2 = f2add(l2, e2);
        }

        float lo, hi, y[8];
        f2unpack(a0, lo, hi); y[0] = lo + hi;
        f2unpack(a1, lo, hi); y[1] = lo + hi;
        f2unpack(a2, lo, hi); y[2] = lo + hi;
        f2unpack(a3, lo, hi); y[3] = lo + hi;
        f2unpack(a4, lo, hi); y[4] = lo + hi;
        f2unpack(a5, lo, hi); y[5] = lo + hi;
        f2unpack(a6, lo, hi); y[6] = lo + hi;
        f2unpack(l2, lo, hi); y[7] = lo + hi;

        float* acc = g_acc + (((size_t)bh * N_TOK + n) << 3);
        #pragma unroll
        for (int i = 0; i < 8; i++) atomicAdd(acc + i, y[i]);   // RED
    }
}

// ---------------- Kernel 2: per-query epilogue (also resets g_work) ---------
__global__ void __launch_bounds__(CTPB) g2_attn_combine(
    const float* __restrict__ o,
    const float* __restrict__ alpha, const float* __restrict__ beta,
    float* __restrict__ out)
{
    if (blockIdx.x == 0 && threadIdx.x == 0) g_work = 0;   // replay-clean

    const int qi = blockIdx.x * CTPB + threadIdx.x;  // 0 .. B*H*N-1
    const int bh = qi >> 11;
    const int n  = qi & (N_TOK - 1);
    const int h  = bh & (N_HEAD - 1);
    const int b  = bh >> 4;

    float* acc = g_acc + ((size_t)qi << 3);
    float4 w0 = *(const float4*)(acc);
    float4 w1 = *(const float4*)(acc + 4);
    float y[7] = {w0.x, w0.y, w0.z, w0.w, w1.x, w1.y, w1.z};
    float l = w1.w;

    // Restore zeros for the next graph replay.
    *(float4*)(acc)     = make_float4(0.f, 0.f, 0.f, 0.f);
    *(float4*)(acc + 4) = make_float4(0.f, 0.f, 0.f, 0.f);

    float rinv = 1.0f / l;
    #pragma unroll
    for (int i = 0; i < 7; i++) y[i] *= rinv;

    const float* obase = o + ((size_t)b * N_TOK) * DMODEL + h * 8;
    float4 q0 = *(const float4*)(obase + (size_t)n * DMODEL);
    float4 q1 = *(const float4*)(obase + (size_t)n * DMODEL + 4);
    float real = q0.x;
    float qo[7] = {q0.y, q0.z, q0.w, q1.x, q1.y, q1.z, q1.w};

    // Octonion cross product c = qo x y.
    float c[7];
    #pragma unroll
    for (int i = 0; i < 7; i++) c[i] = 0.0f;
    const int FI[7] = {0, 0, 0, 1, 1, 2, 2};
    const int FJ[7] = {1, 3, 6, 3, 4, 3, 5};
    const int FK[7] = {2, 4, 5, 5, 6, 6, 4};
    #pragma unroll
    for (int t = 0; t < 7; t++) {
        int i = FI[t], j = FJ[t], k = FK[t];
        c[k] += qo[i] * y[j] - qo[j] * y[i];
        c[i] += qo[j] * y[k] - qo[k] * y[j];
        c[j] += qo[k] * y[i] - qo[i] * y[k];
    }

    float av = 1.0f / (1.0f + __expf(-alpha[h]));
    float bv = tanhf(beta[h]);

    float im[7];
    float ns = real * real;
    #pragma unroll
    for (int i = 0; i < 7; i++) {
        im[i] = av * y[i] + bv * c[i];
        ns += im[i] * im[i];
    }
    float inv = 1.0f / fmaxf(sqrtf(ns), 1e-12f);

    float* op = out + ((size_t)(b * N_TOK + n)) * DMODEL + h * 8;
    *(float4*)(op)     = make_float4(real * inv, im[0] * inv, im[1] * inv, im[2] * inv);
    *(float4*)(op + 4) = make_float4(im[3] * inv, im[4] * inv, im[5] * inv, im[6] * inv);
}

extern "C" void kernel_launch(void* const* d_in, const int* in_sizes, int n_in,
                              void* d_out, int out_size) {
    const float* o     = (const float*)d_in[0];
    const float* mix   = (const float*)d_in[1];
    const float* alpha = (const float*)d_in[2];
    const float* beta  = (const float*)d_in[3];
    float* out = (float*)d_out;
    (void)in_sizes; (void)n_in; (void)out_size;

    g2_attn_partial<<<NWORKER, TPB>>>(o, mix);               // 592 persistent CTAs

    int total = N_BATCH * N_HEAD * N_TOK;                    // 65536 queries
    g2_attn_combine<<<total / CTPB, CTPB>>>(o, alpha, beta, out);
}

// round 12
// speedup vs baseline: 1.1069x; 1.1069x over previous
#include <cuda_runtime.h>

// G2InvariantAttention — GB300 sm_103a — Round 12: R8 base (best measured
// structure) + PDL overlap for the combine.
//   * partial = R8 verbatim (KSPLIT=8, occ cap 4, unroll 2, REDG into 2MB acc).
//   * combine: TPB=64 (best measured), launched with Programmatic Dependent
//     Launch (programmatic stream serialization). It front-loads everything
//     that does NOT depend on the partial (q rows, alpha/beta, index math),
//     then cudaGridDependencySynchronize() before reading g_acc. No explicit
//     trigger in the primary -> implicit trigger at completion -> standard
//     memory visibility for the REDs.
// Exact math: oct_cross(k,k)=0, v==k, scale folded into q, no max-subtraction
// (logits bounded), linear partial combination via REDG.

#define N_TOK   2048
#define N_HEAD  16
#define N_BATCH 2
#define DMODEL  128
#define TPB     256
#define CTPB    64
#define KSPLIT  8
#define KCHUNK  (N_TOK / KSPLIT)      // 256 keys per CTA
#define NPAIR   (KCHUNK / 2)          // 128 key pairs

typedef unsigned long long u64;

// Per-query accumulator: [B*H*N][8 floats] = 2 MB. Zero-init at module load;
// the combine kernel re-zeros after reading -> deterministic across replays.
__device__ float g_acc[(size_t)N_BATCH * N_HEAD * N_TOK * 8];

__device__ __forceinline__ u64 f2pack(float lo, float hi) {
    u64 r; asm("mov.b64 %0,{%1,%2};" : "=l"(r) : "f"(lo), "f"(hi)); return r;
}
__device__ __forceinline__ void f2unpack(u64 v, float& lo, float& hi) {
    asm("mov.b64 {%0,%1},%2;" : "=f"(lo), "=f"(hi) : "l"(v));
}
__device__ __forceinline__ u64 f2fma(u64 a, u64 b, u64 c) {
    u64 d; asm("fma.rn.f32x2 %0,%1,%2,%3;" : "=l"(d) : "l"(a), "l"(b), "l"(c)); return d;
}
__device__ __forceinline__ u64 f2mul(u64 a, u64 b) {
    u64 d; asm("mul.rn.f32x2 %0,%1,%2;" : "=l"(d) : "l"(a), "l"(b)); return d;
}
__device__ __forceinline__ u64 f2add(u64 a, u64 b) {
    u64 d; asm("add.rn.f32x2 %0,%1,%2;" : "=l"(d) : "l"(a), "l"(b)); return d;
}
__device__ __forceinline__ float fast_ex2(float x) {
    float r; asm("ex2.approx.f32 %0,%1;" : "=f"(r) : "f"(x)); return r;
}

// ---------------- Kernel 1: partial attention over a 256-key slice ----------
__global__ void __launch_bounds__(TPB, 4) g2_attn_partial(
    const float* __restrict__ o, const float* __restrict__ mix)
{
    // Pair-major layout: sP[pair][dim][parity], dims 0..6, slot 7 = pad.
    __shared__ float sP[NPAIR * 16];   // 8 KB

    const int bh  = blockIdx.y;
    const int h   = bh & (N_HEAD - 1);
    const int b   = bh >> 4;
    const int ks  = blockIdx.z;
    const int tid = threadIdx.x;
    const float* obase = o + ((size_t)b * N_TOK) * DMODEL + h * 8;

    // Each thread loads one key of this CTA's slice, scatters into pair layout.
    {
        int j  = tid;                       // 0..255 == KCHUNK
        int jg = ks * KCHUNK + j;
        float4 v0 = *(const float4*)(obase + (size_t)jg * DMODEL);      // real,i0,i1,i2
        float4 v1 = *(const float4*)(obase + (size_t)jg * DMODEL + 4);  // i3..i6
        float* dst = sP + (j >> 1) * 16 + (j & 1);
        dst[0]  = v0.y;  dst[2]  = v0.z;  dst[4]  = v0.w;  dst[6]  = v1.x;
        dst[8]  = v1.y;  dst[10] = v1.z;  dst[12] = v1.w;  dst[14] = 0.0f;  // pad
    }
    __syncthreads();

    const int n = blockIdx.x * TPB + tid;

    // w_k = sigmoid(m0-m1); fold w_k * log2e / sqrt(7) into q.
    float m0 = mix[2 * h], m1 = mix[2 * h + 1];
    float wk = 1.0f / (1.0f + __expf(m1 - m0));
    const float coef = wk * 1.4426950408889634f * 0.3779644730092272f;

    float4 q0 = *(const float4*)(obase + (size_t)n * DMODEL);
    float4 q1 = *(const float4*)(obase + (size_t)n * DMODEL + 4);
    u64 qd0 = f2pack(q0.y * coef, q0.y * coef);
    u64 qd1 = f2pack(q0.z * coef, q0.z * coef);
    u64 qd2 = f2pack(q0.w * coef, q0.w * coef);
    u64 qd3 = f2pack(q1.x * coef, q1.x * coef);
    u64 qd4 = f2pack(q1.y * coef, q1.y * coef);
    u64 qd5 = f2pack(q1.z * coef, q1.z * coef);
    u64 qd6 = f2pack(q1.w * coef, q1.w * coef);

    u64 a0 = 0ULL, a1 = 0ULL, a2 = 0ULL, a3 = 0ULL, a4 = 0ULL, a5 = 0ULL, a6 = 0ULL;
    u64 l2 = 0ULL;   // packed (sum e even keys, sum e odd keys)

    unsigned sbase;
    asm("{ .reg .u64 t; cvta.to.shared.u64 t, %1; cvt.u32.u64 %0, t; }"
        : "=r"(sbase) : "l"(sP));

    unsigned addr = sbase;
    #pragma unroll 2
    for (int p = 0; p < NPAIR; p++, addr += 64) {
        u64 P0, P1, P2, P3, P4, P5, P6, P7;
        asm("ld.shared.v2.b64 {%0,%1},[%2];" : "=l"(P0), "=l"(P1) : "r"(addr));
        asm("ld.shared.v2.b64 {%0,%1},[%2];" : "=l"(P2), "=l"(P3) : "r"(addr + 16));
        asm("ld.shared.v2.b64 {%0,%1},[%2];" : "=l"(P4), "=l"(P5) : "r"(addr + 32));
        asm("ld.shared.v2.b64 {%0,%1},[%2];" : "=l"(P6), "=l"(P7) : "r"(addr + 48));
        (void)P7;
        u64 s = f2mul(qd0, P0);
        s = f2fma(qd1, P1, s);
        s = f2fma(qd2, P2, s);
        s = f2fma(qd3, P3, s);
        s = f2fma(qd4, P4, s);
        s = f2fma(qd5, P5, s);
        s = f2fma(qd6, P6, s);
        float sa, sb; f2unpack(s, sa, sb);
        float ea = fast_ex2(sa);
        float eb = fast_ex2(sb);
        u64 e2 = f2pack(ea, eb);
        a0 = f2fma(P0, e2, a0);
        a1 = f2fma(P1, e2, a1);
        a2 = f2fma(P2, e2, a2);
        a3 = f2fma(P3, e2, a3);
        a4 = f2fma(P4, e2, a4);
        a5 = f2fma(P5, e2, a5);
        a6 = f2fma(P6, e2, a6);
        l2 = f2add(l2, e2);
    }

    // Horizontal sums -> (y0..y6, l); accumulate into per-query slot via REDG.
    float lo, hi, y[8];
    f2unpack(a0, lo, hi); y[0] = lo + hi;
    f2unpack(a1, lo, hi); y[1] = lo + hi;
    f2unpack(a2, lo, hi); y[2] = lo + hi;
    f2unpack(a3, lo, hi); y[3] = lo + hi;
    f2unpack(a4, lo, hi); y[4] = lo + hi;
    f2unpack(a5, lo, hi); y[5] = lo + hi;
    f2unpack(a6, lo, hi); y[6] = lo + hi;
    f2unpack(l2, lo, hi); y[7] = lo + hi;

    float* acc = g_acc + (((size_t)bh * N_TOK + n) << 3);
    #pragma unroll
    for (int i = 0; i < 8; i++) atomicAdd(acc + i, y[i]);   // RED, no return
}

// ---------------- Kernel 2: PDL epilogue (loads q early, syncs, reads acc) --
__global__ void __launch_bounds__(CTPB) g2_attn_combine(
    const float* __restrict__ o,
    const float* __restrict__ alpha, const float* __restrict__ beta,
    float* __restrict__ out)
{
    const int qi = blockIdx.x * CTPB + threadIdx.x;  // 0 .. B*H*N-1
    const int bh = qi >> 11;
    const int n  = qi & (N_TOK - 1);
    const int h  = bh & (N_HEAD - 1);
    const int b  = bh >> 4;

    // ---- Independent of the partial: issue these loads BEFORE the sync.
    const float* obase = o + ((size_t)b * N_TOK) * DMODEL + h * 8;
    float4 q0 = *(const float4*)(obase + (size_t)n * DMODEL);
    float4 q1 = *(const float4*)(obase + (size_t)n * DMODEL + 4);
    float av = 1.0f / (1.0f + __expf(-alpha[h]));
    float bv = tanhf(beta[h]);

    // ---- Wait for the partial grid to complete (PDL).
    cudaGridDependencySynchronize();

    float* acc = g_acc + ((size_t)qi << 3);
    float4 w0 = *(const float4*)(acc);
    float4 w1 = *(const float4*)(acc + 4);
    float y[7] = {w0.x, w0.y, w0.z, w0.w, w1.x, w1.y, w1.z};
    float l = w1.w;

    // Restore zeros for the next graph replay (deterministic state).
    *(float4*)(acc)     = make_float4(0.f, 0.f, 0.f, 0.f);
    *(float4*)(acc + 4) = make_float4(0.f, 0.f, 0.f, 0.f);

    float rinv = 1.0f / l;
    #pragma unroll
    for (int i = 0; i < 7; i++) y[i] *= rinv;

    float real = q0.x;
    float qo[7] = {q0.y, q0.z, q0.w, q1.x, q1.y, q1.z, q1.w};

    // Octonion cross product c = qo x y.
    float c[7];
    #pragma unroll
    for (int i = 0; i < 7; i++) c[i] = 0.0f;
    const int FI[7] = {0, 0, 0, 1, 1, 2, 2};
    const int FJ[7] = {1, 3, 6, 3, 4, 3, 5};
    const int FK[7] = {2, 4, 5, 5, 6, 6, 4};
    #pragma unroll
    for (int t = 0; t < 7; t++) {
        int i = FI[t], j = FJ[t], k = FK[t];
        c[k] += qo[i] * y[j] - qo[j] * y[i];
        c[i] += qo[j] * y[k] - qo[k] * y[j];
        c[j] += qo[k] * y[i] - qo[i] * y[k];
    }

    float im[7];
    float ns = real * real;
    #pragma unroll
    for (int i = 0; i < 7; i++) {
        im[i] = av * y[i] + bv * c[i];
        ns += im[i] * im[i];
    }
    float inv = 1.0f / fmaxf(sqrtf(ns), 1e-12f);

    float* op = out + ((size_t)(b * N_TOK + n)) * DMODEL + h * 8;
    *(float4*)(op)     = make_float4(real * inv, im[0] * inv, im[1] * inv, im[2] * inv);
    *(float4*)(op + 4) = make_float4(im[3] * inv, im[4] * inv, im[5] * inv, im[6] * inv);
}

extern "C" void kernel_launch(void* const* d_in, const int* in_sizes, int n_in,
                              void* d_out, int out_size) {
    const float* o     = (const float*)d_in[0];
    const float* mix   = (const float*)d_in[1];
    const float* alpha = (const float*)d_in[2];
    const float* beta  = (const float*)d_in[3];
    float* out = (float*)d_out;
    (void)in_sizes; (void)n_in; (void)out_size;

    dim3 grid1(N_TOK / TPB, N_BATCH * N_HEAD, KSPLIT);   // (8, 32, 8) = 2048 CTAs
    g2_attn_partial<<<grid1, TPB>>>(o, mix);

    // Combine with Programmatic Dependent Launch: launches while the partial
    // drains; cudaGridDependencySynchronize() inside gates the acc reads.
    cudaLaunchConfig_t cfg = {};
    cfg.gridDim  = dim3(N_BATCH * N_HEAD * N_TOK / CTPB, 1, 1);   // 1024 CTAs
    cfg.blockDim = dim3(CTPB, 1, 1);
    cudaLaunchAttribute attrs[1];
    attrs[0].id = cudaLaunchAttributeProgrammaticStreamSerialization;
    attrs[0].val.programmaticStreamSerializationAllowed = 1;
    cfg.attrs = attrs;
    cfg.numAttrs = 1;
    cudaLaunchKernelEx(&cfg, g2_attn_combine, o, alpha, beta, out);
}